// round 4
// baseline (speedup 1.0000x reference)
#include <cuda_runtime.h>
#include <cuda_bf16.h>

#define N_NODES 10000
#define N_EDGES 160000
#define D1 128
#define D2 256
#define D3 512

// Scratch (no allocs allowed): per-node scalars + collapsed weight vectors.
__device__ float g_g1[N_NODES];
__device__ float g_s [N_NODES];
__device__ float g_a2[N_NODES];
__device__ float g_a3[N_NODES];
__device__ float g_t [N_NODES];
__device__ __align__(16) float g_P[D3];
__device__ __align__(16) float g_Q[D3];
__device__ __align__(16) float g_R[D3];

// Kernel A: zero node scalars (blocks 1..) and collapse weights (block 0).
//   W12[k] = sum_j W1[j]*W2[j,k]       (j<128, k<256)
//   bW2[k] = sum_j b1[j]*W2[j,k]
//   P[m] = sum_k W12[k]*W3[k,m]        (m<512)
//   Q[m] = sum_k bW2[k]*W3[k,m]
//   R[m] = sum_k b2[k] *W3[k,m]
__global__ void prep_kernel(const float* __restrict__ W1, const float* __restrict__ b1,
                            const float* __restrict__ W2, const float* __restrict__ b2,
                            const float* __restrict__ W3) {
    if (blockIdx.x == 0) {
        __shared__ float sW12[D2];
        __shared__ float sbW2[D2];
        int t = threadIdx.x;  // 512 threads
        if (t < D2) {
            float acc = 0.f, accb = 0.f;
            #pragma unroll 4
            for (int j = 0; j < D1; j++) {
                float w2 = W2[j * D2 + t];
                acc  += W1[j] * w2;
                accb += b1[j] * w2;
            }
            sW12[t] = acc;
            sbW2[t] = accb;
        }
        __syncthreads();
        float p = 0.f, q = 0.f, r = 0.f;
        #pragma unroll 4
        for (int k = 0; k < D2; k++) {
            float w3 = W3[k * D3 + t];
            p += sW12[k] * w3;
            q += sbW2[k] * w3;
            r += b2[k]   * w3;
        }
        g_P[t] = p; g_Q[t] = q; g_R[t] = r;
    } else {
        int i = (blockIdx.x - 1) * blockDim.x + threadIdx.x;
        if (i < N_NODES) {
            g_g1[i] = 0.f; g_s[i] = 0.f; g_a2[i] = 0.f; g_a3[i] = 0.f; g_t[i] = 0.f;
        }
    }
}

// Edge pass 1: g1[dst] += ew*x[src];  s[dst] += ew
// edge_index is int32 (JAX demotes int64 with x64 disabled).
__global__ void edge_pass1(const float* __restrict__ x,
                           const int* __restrict__ ei,
                           const float* __restrict__ ew) {
    int e = blockIdx.x * blockDim.x + threadIdx.x;
    if (e < N_EDGES) {
        int src = ei[e];
        int dst = ei[N_EDGES + e];
        float w = ew[e];
        atomicAdd(&g_g1[dst], w * x[src]);
        atomicAdd(&g_s[dst], w);
    }
}

// Edge pass 2: a2[dst] += ew*g1[src]
__global__ void edge_pass2(const int* __restrict__ ei,
                           const float* __restrict__ ew) {
    int e = blockIdx.x * blockDim.x + threadIdx.x;
    if (e < N_EDGES) {
        int src = ei[e];
        int dst = ei[N_EDGES + e];
        float w = ew[e];
        atomicAdd(&g_a2[dst], w * g_g1[src]);
    }
}

// Edge pass 3: a3[dst] += ew*a2[src];  t[dst] += ew*s[src]
__global__ void edge_pass3(const int* __restrict__ ei,
                           const float* __restrict__ ew) {
    int e = blockIdx.x * blockDim.x + threadIdx.x;
    if (e < N_EDGES) {
        int src = ei[e];
        int dst = ei[N_EDGES + e];
        float w = ew[e];
        atomicAdd(&g_a3[dst], w * g_a2[src]);
        atomicAdd(&g_t[dst],  w * g_s[src]);
    }
}

// Output: out[n,m] = sigmoid(a3[n]*P[m] + t[n]*Q[m] + s[n]*R[m] + b3[m])
// One thread per float4 (128 float4 per node row).
__global__ void out_kernel(const float* __restrict__ b3, float* __restrict__ out) {
    int idx = blockIdx.x * blockDim.x + threadIdx.x;   // [0, N_NODES*128)
    if (idx >= N_NODES * (D3 / 4)) return;
    int n  = idx >> 7;           // /128
    int j4 = (idx & 127) << 2;   // feature base

    float a3 = g_a3[n];
    float tt = g_t[n];
    float ss = g_s[n];

    float4 P  = *reinterpret_cast<const float4*>(&g_P[j4]);
    float4 Q  = *reinterpret_cast<const float4*>(&g_Q[j4]);
    float4 R  = *reinterpret_cast<const float4*>(&g_R[j4]);
    float4 B  = *reinterpret_cast<const float4*>(&b3[j4]);

    float4 v;
    v.x = fmaf(a3, P.x, fmaf(tt, Q.x, fmaf(ss, R.x, B.x)));
    v.y = fmaf(a3, P.y, fmaf(tt, Q.y, fmaf(ss, R.y, B.y)));
    v.z = fmaf(a3, P.z, fmaf(tt, Q.z, fmaf(ss, R.z, B.z)));
    v.w = fmaf(a3, P.w, fmaf(tt, Q.w, fmaf(ss, R.w, B.w)));

    v.x = 1.f / (1.f + __expf(-v.x));
    v.y = 1.f / (1.f + __expf(-v.y));
    v.z = 1.f / (1.f + __expf(-v.z));
    v.w = 1.f / (1.f + __expf(-v.w));

    *reinterpret_cast<float4*>(&out[n * D3 + j4]) = v;
}

extern "C" void kernel_launch(void* const* d_in, const int* in_sizes, int n_in,
                              void* d_out, int out_size) {
    const float* x  = (const float*)d_in[0];
    const int*   ei = (const int*)d_in[1];
    const float* ew = (const float*)d_in[2];
    const float* W1 = (const float*)d_in[3];
    const float* b1 = (const float*)d_in[4];
    const float* W2 = (const float*)d_in[5];
    const float* b2 = (const float*)d_in[6];
    const float* W3 = (const float*)d_in[7];
    const float* b3 = (const float*)d_in[8];
    float* out = (float*)d_out;

    // prep: block 0 = weight collapse (512 thr), blocks 1..N zero node arrays
    int zero_blocks = (N_NODES + 511) / 512;
    prep_kernel<<<1 + zero_blocks, 512>>>(W1, b1, W2, b2, W3);

    int eb = (N_EDGES + 255) / 256;
    edge_pass1<<<eb, 256>>>(x, ei, ew);
    edge_pass2<<<eb, 256>>>(ei, ew);
    edge_pass3<<<eb, 256>>>(ei, ew);

    int total4 = N_NODES * (D3 / 4);
    out_kernel<<<(total4 + 255) / 256, 256>>>(b3, out);
}

// round 6
// speedup vs baseline: 1.2892x; 1.2892x over previous
#include <cuda_runtime.h>

#define N_NODES 10000
#define N_EDGES 160000
#define D1 128
#define D2 256
#define D3 512

#define GRID 148
#define TPB  1024
#define GT   (GRID * TPB)   // 151552 threads

// ---- persistent scratch (__device__ globals; no allocs allowed) ----
// node scalars packed: [g1 | s | a2 | a3 | t]
__device__ float g_nodes[5 * N_NODES];
__device__ float g_W12[D2];     // W1 @ W2
__device__ float g_bW2[D2];     // b1 @ W2
// collapsed weight vectors packed [P | Q | R], 16B-aligned for float4 reads
__device__ __align__(16) float g_PQR[3 * D3];

// ---- grid barrier state (invariant: count==0 between barriers) ----
__device__ int g_bar_count;
__device__ volatile int g_bar_gen;

__device__ __forceinline__ void grid_bar() {
    __threadfence();            // make this thread's ST/RED globally visible
    __syncthreads();
    if (threadIdx.x == 0) {
        int gen = g_bar_gen;    // snapshot BEFORE arriving
        if (atomicAdd(&g_bar_count, 1) == GRID - 1) {
            g_bar_count = 0;    // reset before release
            __threadfence();
            g_bar_gen = gen + 1;
        } else {
            while (g_bar_gen == gen) { __nanosleep(40); }
        }
    }
    __syncthreads();
}

__global__ void __launch_bounds__(TPB, 1)
fused_gcn_kernel(const float* __restrict__ x,
                 const int*   __restrict__ ei,
                 const float* __restrict__ ew,
                 const float* __restrict__ W1,
                 const float* __restrict__ b1,
                 const float* __restrict__ W2,
                 const float* __restrict__ b2,
                 const float* __restrict__ W3,
                 const float* __restrict__ b3,
                 float* __restrict__ out) {
    __shared__ float s_red[4][D2];

    const int tid  = threadIdx.x;
    const int bid  = blockIdx.x;
    const int gtid = bid * TPB + tid;

    float* G1 = g_nodes;
    float* S  = g_nodes + N_NODES;
    float* A2 = g_nodes + 2 * N_NODES;
    float* A3 = g_nodes + 3 * N_NODES;
    float* T  = g_nodes + 4 * N_NODES;

    // ================= Phase A: zero scratch; W12 = W1@W2, bW2 = b1@W2 ======
    if (gtid < 5 * N_NODES) g_nodes[gtid] = 0.f;
    else if (gtid < 5 * N_NODES + 3 * D3) g_PQR[gtid - 5 * N_NODES] = 0.f;

    if (bid < 2) {
        // 1024 threads = 256 k-columns x 4 j-chunks of 32
        const float* a = (bid == 0) ? W1 : b1;
        int k  = tid & (D2 - 1);
        int jc = tid >> 8;            // 0..3
        int j0 = jc * 32;
        float acc = 0.f;
        #pragma unroll 8
        for (int jj = 0; jj < 32; jj++) {
            int j = j0 + jj;
            acc += a[j] * W2[j * D2 + k];
        }
        s_red[jc][k] = acc;
        __syncthreads();
        if (tid < D2) {
            float v = s_red[0][tid] + s_red[1][tid] + s_red[2][tid] + s_red[3][tid];
            if (bid == 0) g_W12[tid] = v;
            else          g_bW2[tid] = v;
        }
    }

    grid_bar();

    // ===== Phase B: edge pass 1 (blocks 0-99) | P/Q/R GEMV (blocks 100-147) =
    if (bid < 100) {
        // g1[dst] += w * x[src];  s[dst] += w
        int e_end = (bid + 1) * 1600;
        for (int e = bid * 1600 + tid; e < e_end; e += TPB) {
            int src = ei[e];
            int dst = ei[N_EDGES + e];
            float w = ew[e];
            atomicAdd(&G1[dst], w * x[src]);
            atomicAdd(&S[dst],  w);
        }
    } else {
        // 48 tasks: vec in {P,Q,R}, 16-row k-chunk of W3; partial into g_PQR
        int task  = bid - 100;          // 0..47
        int vec   = task >> 4;          // /16
        int chunk = task & 15;
        if (tid < D3) {
            const float* coef = (vec == 0) ? g_W12 : ((vec == 1) ? g_bW2 : b2);
            int k0 = chunk * 16;
            float acc = 0.f;
            #pragma unroll
            for (int kk = 0; kk < 16; kk++) {
                int k = k0 + kk;
                acc += coef[k] * W3[k * D3 + tid];
            }
            atomicAdd(&g_PQR[vec * D3 + tid], acc);
        }
    }

    grid_bar();

    // ===== Phase C: edge pass 2: a2[dst] += w*g1[src];  t[dst] += w*s[src] ==
    for (int e = gtid; e < N_EDGES; e += GT) {
        int src = ei[e];
        int dst = ei[N_EDGES + e];
        float w = ew[e];
        atomicAdd(&A2[dst], w * G1[src]);
        atomicAdd(&T[dst],  w * S[src]);
    }

    grid_bar();

    // ===== Phase D: edge pass 3: a3[dst] += w*a2[src] =======================
    for (int e = gtid; e < N_EDGES; e += GT) {
        int src = ei[e];
        int dst = ei[N_EDGES + e];
        float w = ew[e];
        atomicAdd(&A3[dst], w * A2[src]);
    }

    grid_bar();

    // ===== Phase E: out[n,m] = sigmoid(a3*P + t*Q + s*R + b3) ===============
    {
        int j4 = (gtid & 127) << 2;     // loop-invariant feature offset
        float4 P = *reinterpret_cast<const float4*>(&g_PQR[j4]);
        float4 Q = *reinterpret_cast<const float4*>(&g_PQR[D3 + j4]);
        float4 R = *reinterpret_cast<const float4*>(&g_PQR[2 * D3 + j4]);
        float4 B = *reinterpret_cast<const float4*>(&b3[j4]);

        for (int n = gtid >> 7; n < N_NODES; n += (GT >> 7)) {
            float a3 = A3[n];
            float tt = T[n];
            float ss = S[n];

            float4 v;
            v.x = fmaf(a3, P.x, fmaf(tt, Q.x, fmaf(ss, R.x, B.x)));
            v.y = fmaf(a3, P.y, fmaf(tt, Q.y, fmaf(ss, R.y, B.y)));
            v.z = fmaf(a3, P.z, fmaf(tt, Q.z, fmaf(ss, R.z, B.z)));
            v.w = fmaf(a3, P.w, fmaf(tt, Q.w, fmaf(ss, R.w, B.w)));

            v.x = __fdividef(1.f, 1.f + __expf(-v.x));
            v.y = __fdividef(1.f, 1.f + __expf(-v.y));
            v.z = __fdividef(1.f, 1.f + __expf(-v.z));
            v.w = __fdividef(1.f, 1.f + __expf(-v.w));

            *reinterpret_cast<float4*>(&out[n * D3 + j4]) = v;
        }
    }
}

extern "C" void kernel_launch(void* const* d_in, const int* in_sizes, int n_in,
                              void* d_out, int out_size) {
    const float* x  = (const float*)d_in[0];
    const int*   ei = (const int*)d_in[1];
    const float* ew = (const float*)d_in[2];
    const float* W1 = (const float*)d_in[3];
    const float* b1 = (const float*)d_in[4];
    const float* W2 = (const float*)d_in[5];
    const float* b2 = (const float*)d_in[6];
    const float* W3 = (const float*)d_in[7];
    const float* b3 = (const float*)d_in[8];
    float* out = (float*)d_out;

    fused_gcn_kernel<<<GRID, TPB>>>(x, ei, ew, W1, b1, W2, b2, W3, b3, out);
}

// round 7
// speedup vs baseline: 1.6828x; 1.3053x over previous
#include <cuda_runtime.h>

#define N_NODES 10000
#define N_EDGES 160000
#define D1 128
#define D2 256
#define D3 512

#define GRID 148
#define TPB  1024
#define GT   (GRID * TPB)   // 151552 threads

// ---- persistent scratch ----
// pair1[n] = (g1[n], s[n]) ; pair2[n] = (a2[n], t[n])
__device__ __align__(16) float2 g_p1[N_NODES];
__device__ __align__(16) float2 g_p2[N_NODES];
__device__ float g_a3[N_NODES];
__device__ float g_W12[D2];     // W1 @ W2
__device__ float g_bW2[D2];     // b1 @ W2
// collapsed, PRE-HALVED weight vectors: [P/2 | Q/2 | R/2 | b3/2]
__device__ __align__(16) float g_PQRB[4 * D3];

// ---- grid barrier (invariant: count==0 between barriers) ----
__device__ int g_bar_count;
__device__ volatile int g_bar_gen;

__device__ __forceinline__ void grid_bar() {
    __threadfence();
    __syncthreads();
    if (threadIdx.x == 0) {
        int gen = g_bar_gen;                 // snapshot BEFORE arriving
        if (atomicAdd(&g_bar_count, 1) == GRID - 1) {
            g_bar_count = 0;
            __threadfence();
            g_bar_gen = gen + 1;
        } else {
            while (g_bar_gen == gen) { }     // tight spin; wakeup ~ L2 RTT
        }
    }
    __syncthreads();
}

__device__ __forceinline__ void red_add_v2(float2* addr, float a, float b) {
    asm volatile("red.global.add.v2.f32 [%0], {%1, %2};"
                 :: "l"(addr), "f"(a), "f"(b) : "memory");
}

__device__ __forceinline__ float fast_tanh(float h) {
    float r;
    asm("tanh.approx.f32 %0, %1;" : "=f"(r) : "f"(h));
    return r;
}

__global__ void __launch_bounds__(TPB, 1)
fused_gcn_kernel(const float* __restrict__ x,
                 const int*   __restrict__ ei,
                 const float* __restrict__ ew,
                 const float* __restrict__ W1,
                 const float* __restrict__ b1,
                 const float* __restrict__ W2,
                 const float* __restrict__ b2,
                 const float* __restrict__ W3,
                 const float* __restrict__ b3,
                 float* __restrict__ out) {
    __shared__ float s_red[4][D2];

    const int tid  = threadIdx.x;
    const int bid  = blockIdx.x;
    const int gtid = bid * TPB + tid;

    // ===== Phase A: zero scratch; W12 = W1@W2, bW2 = b1@W2; B = b3/2 ========
    {
        if (gtid < 2 * N_NODES)                 ((float*)g_p1)[gtid] = 0.f;
        else if (gtid < 4 * N_NODES)            ((float*)g_p2)[gtid - 2 * N_NODES] = 0.f;
        else if (gtid < 5 * N_NODES)            g_a3[gtid - 4 * N_NODES] = 0.f;
        else if (gtid < 5 * N_NODES + 3 * D3)   g_PQRB[gtid - 5 * N_NODES] = 0.f;

        if (bid < 2) {
            // 1024 threads = 256 k-columns x 4 j-chunks of 32
            const float* a = (bid == 0) ? W1 : b1;
            int k  = tid & (D2 - 1);
            int jc = tid >> 8;
            int j0 = jc * 32;
            float acc = 0.f;
            #pragma unroll 8
            for (int jj = 0; jj < 32; jj++) {
                int j = j0 + jj;
                acc += a[j] * W2[j * D2 + k];
            }
            s_red[jc][k] = acc;
            __syncthreads();
            if (tid < D2) {
                float v = s_red[0][tid] + s_red[1][tid] + s_red[2][tid] + s_red[3][tid];
                if (bid == 0) g_W12[tid] = v;
                else          g_bW2[tid] = v;
            }
        } else if (bid == 2) {
            if (tid < D3) g_PQRB[3 * D3 + tid] = 0.5f * b3[tid];
        }
    }

    grid_bar();

    // ===== Phase B: edge pass 1 (blocks 0-99) | P/Q/R GEMV (blocks 100-147) =
    if (bid < 100) {
        // (g1,s)[dst] += (w*x[src], w)
        int e_end = (bid + 1) * 1600;
        for (int e = bid * 1600 + tid; e < e_end; e += TPB) {
            int src = ei[e];
            int dst = ei[N_EDGES + e];
            float w = ew[e];
            red_add_v2(&g_p1[dst], w * x[src], w);
        }
    } else {
        // 48 tasks: vec in {P,Q,R} x 16-row k-chunk of W3; accumulate halved
        int task  = bid - 100;
        int vec   = task >> 4;
        int chunk = task & 15;
        if (tid < D3) {
            const float* coef = (vec == 0) ? g_W12 : ((vec == 1) ? g_bW2 : b2);
            int k0 = chunk * 16;
            float acc = 0.f;
            #pragma unroll
            for (int kk = 0; kk < 16; kk++) {
                int k = k0 + kk;
                acc += coef[k] * W3[k * D3 + tid];
            }
            atomicAdd(&g_PQRB[vec * D3 + tid], 0.5f * acc);
        }
    }

    grid_bar();

    // ===== Phase C: (a2,t)[dst] += w*(g1,s)[src]  (cache edge triples) ======
    int src0 = ei[gtid];
    int dst0 = ei[N_EDGES + gtid];
    float w0 = ew[gtid];
    int src1 = 0, dst1 = 0; float w1 = 0.f;
    const bool has1 = (gtid + GT) < N_EDGES;
    if (has1) {
        src1 = ei[gtid + GT];
        dst1 = ei[N_EDGES + gtid + GT];
        w1   = ew[gtid + GT];
    }
    {
        float2 p = g_p1[src0];
        red_add_v2(&g_p2[dst0], w0 * p.x, w0 * p.y);
        if (has1) {
            float2 q = g_p1[src1];
            red_add_v2(&g_p2[dst1], w1 * q.x, w1 * q.y);
        }
    }

    grid_bar();

    // ===== Phase D: a3[dst] += w * a2[src] (reuse cached triples) ===========
    {
        atomicAdd(&g_a3[dst0], w0 * g_p2[src0].x);
        if (has1) atomicAdd(&g_a3[dst1], w1 * g_p2[src1].x);
    }

    grid_bar();

    // ===== Phase E: out = 0.5*tanh(a3*P' + t*Q' + s*R' + B') + 0.5 ==========
    {
        int j4 = (gtid & 127) << 2;     // loop-invariant feature offset
        float4 P = *reinterpret_cast<const float4*>(&g_PQRB[j4]);
        float4 Q = *reinterpret_cast<const float4*>(&g_PQRB[D3 + j4]);
        float4 R = *reinterpret_cast<const float4*>(&g_PQRB[2 * D3 + j4]);
        float4 B = *reinterpret_cast<const float4*>(&g_PQRB[3 * D3 + j4]);

        for (int n = gtid >> 7; n < N_NODES; n += (GT >> 7)) {
            float a3 = g_a3[n];
            float2 p2 = g_p2[n];   // (a2, t)
            float2 p1 = g_p1[n];   // (g1, s)
            float tt = p2.y;
            float ss = p1.y;

            float4 v;  // = raw_logit / 2  (weights pre-halved)
            v.x = fmaf(a3, P.x, fmaf(tt, Q.x, fmaf(ss, R.x, B.x)));
            v.y = fmaf(a3, P.y, fmaf(tt, Q.y, fmaf(ss, R.y, B.y)));
            v.z = fmaf(a3, P.z, fmaf(tt, Q.z, fmaf(ss, R.z, B.z)));
            v.w = fmaf(a3, P.w, fmaf(tt, Q.w, fmaf(ss, R.w, B.w)));

            v.x = fmaf(0.5f, fast_tanh(v.x), 0.5f);
            v.y = fmaf(0.5f, fast_tanh(v.y), 0.5f);
            v.z = fmaf(0.5f, fast_tanh(v.z), 0.5f);
            v.w = fmaf(0.5f, fast_tanh(v.w), 0.5f);

            *reinterpret_cast<float4*>(&out[n * D3 + j4]) = v;
        }
    }
}

extern "C" void kernel_launch(void* const* d_in, const int* in_sizes, int n_in,
                              void* d_out, int out_size) {
    const float* x  = (const float*)d_in[0];
    const int*   ei = (const int*)d_in[1];
    const float* ew = (const float*)d_in[2];
    const float* W1 = (const float*)d_in[3];
    const float* b1 = (const float*)d_in[4];
    const float* W2 = (const float*)d_in[5];
    const float* b2 = (const float*)d_in[6];
    const float* W3 = (const float*)d_in[7];
    const float* b3 = (const float*)d_in[8];
    float* out = (float*)d_out;

    fused_gcn_kernel<<<GRID, TPB>>>(x, ei, ew, W1, b1, W2, b2, W3, b3, out);
}